// round 2
// baseline (speedup 1.0000x reference)
#include <cuda_runtime.h>
#include <cuda_fp16.h>

#define N_NODES 4096
#define IN_F    256
#define HEADS   8
#define HID     32
#define OUTF    256
#define NCHUNK  4
#define JT      128
#define ITILE   64
#define JCHUNK  (N_NODES / NCHUNK)

// ---------------- device scratch (no allocs allowed) ----------------
__device__ __align__(16) float  g_f32[N_NODES * OUTF];          // g = h@W, fp32
__device__ __align__(16) __half g_h_t[OUTF * N_NODES];          // g transposed per (h,f): [h*32+f][n], fp16
__device__ __align__(16) float  nsrc_g[HEADS * N_NODES];        // -s_src
__device__ __align__(16) float  Pg[HEADS * N_NODES];            // exp(s_src)
__device__ __align__(16) float  Rg[HEADS * N_NODES];            // exp(0.2*s_src)
__device__ __align__(16) float4 jvec_g[HEADS * N_NODES];        // (s_dst, exp(s_dst), exp(0.2*s_dst), 0)
__device__ __align__(16) float  num_part[NCHUNK][N_NODES][OUTF];
__device__ __align__(16) float  z_part[NCHUNK][HEADS][N_NODES];

// ---------------- kernel 1: g = h @ W (fp32 tiled GEMM) ----------------
__global__ __launch_bounds__(256) void gemm_g(const float* __restrict__ h,
                                              const float* __restrict__ W) {
    __shared__ float As[16][65];
    __shared__ float Bs[16][65];
    int tx = threadIdx.x & 15, ty = threadIdx.x >> 4;
    int i0 = blockIdx.y * 64, n0 = blockIdx.x * 64;
    float acc[4][4] = {};
    for (int k0 = 0; k0 < IN_F; k0 += 16) {
        for (int idx = threadIdx.x; idx < 64 * 16; idx += 256) {
            int r = idx >> 4, kk = idx & 15;
            As[kk][r] = h[(size_t)(i0 + r) * IN_F + k0 + kk];
        }
        for (int idx = threadIdx.x; idx < 16 * 64; idx += 256) {
            int kk = idx >> 6, c = idx & 63;
            Bs[kk][c] = W[(size_t)(k0 + kk) * OUTF + n0 + c];
        }
        __syncthreads();
#pragma unroll
        for (int kk = 0; kk < 16; kk++) {
            float av[4], bv[4];
#pragma unroll
            for (int u = 0; u < 4; u++) av[u] = As[kk][ty * 4 + u];
#pragma unroll
            for (int v = 0; v < 4; v++) bv[v] = Bs[kk][tx * 4 + v];
#pragma unroll
            for (int u = 0; u < 4; u++)
#pragma unroll
                for (int v = 0; v < 4; v++) acc[u][v] += av[u] * bv[v];
        }
        __syncthreads();
    }
#pragma unroll
    for (int u = 0; u < 4; u++)
#pragma unroll
        for (int v = 0; v < 4; v++)
            g_f32[(size_t)(i0 + ty * 4 + u) * OUTF + n0 + tx * 4 + v] = acc[u][v];
}

// ---------------- kernel 1b: per-node scores, exps, fp16 transpose ----------------
__global__ __launch_bounds__(256) void node_stats(const float* __restrict__ a) {
    int warp = threadIdx.x >> 5, lane = threadIdx.x & 31;
    int n = blockIdx.x * 8 + warp;
    float gv[8];
#pragma unroll
    for (int c = 0; c < 8; c++) gv[c] = g_f32[(size_t)n * OUTF + c * 32 + lane];
    float as = a[lane], ad = a[32 + lane];
#pragma unroll
    for (int hh = 0; hh < 8; hh++) {
        float vs = gv[hh] * as, vd = gv[hh] * ad;
#pragma unroll
        for (int o = 16; o; o >>= 1) {
            vs += __shfl_xor_sync(0xffffffffu, vs, o);
            vd += __shfl_xor_sync(0xffffffffu, vd, o);
        }
        if (lane == 0) {
            nsrc_g[hh * N_NODES + n] = -vs;
            Pg[hh * N_NODES + n]     = expf(vs);
            Rg[hh * N_NODES + n]     = expf(0.2f * vs);
            jvec_g[hh * N_NODES + n] = make_float4(vd, expf(vd), expf(0.2f * vd), 0.f);
        }
        g_h_t[(size_t)(hh * 32 + lane) * N_NODES + n] = __float2half(gv[hh]);
    }
}

// ---------------- kernel 2: fused masked-softmax aggregation ----------------
__device__ __forceinline__ unsigned pack2(float lo, float hi) {
    __half2 hx = __floats2half2_rn(lo, hi);
    return *reinterpret_cast<unsigned*>(&hx);
}

__device__ __forceinline__ void mma16816(float* c, unsigned a0, unsigned a1,
                                         unsigned a2, unsigned a3,
                                         unsigned b0, unsigned b1) {
    asm volatile(
        "mma.sync.aligned.m16n8k16.row.col.f32.f16.f16.f32 "
        "{%0,%1,%2,%3}, {%4,%5,%6,%7}, {%8,%9}, {%0,%1,%2,%3};"
        : "+f"(c[0]), "+f"(c[1]), "+f"(c[2]), "+f"(c[3])
        : "r"(a0), "r"(a1), "r"(a2), "r"(a3), "r"(b0), "r"(b1));
}

__device__ __forceinline__ float wcalc(const float4& p, float ns, float Pv, float Rv,
                                       unsigned bit) {
    float v = (p.x >= ns) ? Pv * p.y : Rv * p.z;
    return bit ? v : 0.f;
}

// smem layout:
//   float4 jpack[8][128]            : 16384 B
//   __half gTs[256][136]            : 69632 B  (row = h*32+f, padded stride 136 halves)
//   unsigned adjb[64][4]            : 1024 B
#define SMEM_JPACK 0
#define SMEM_GT    16384
#define SMEM_ADJB  (16384 + 69632)
#define SMEM2_SZ   (16384 + 69632 + 1024)

extern __shared__ char smem2[];

__global__ __launch_bounds__(256, 1) void attn_agg(const int* __restrict__ adj) {
    float4*   jpack = (float4*)(smem2 + SMEM_JPACK);
    __half*   gTs   = (__half*)(smem2 + SMEM_GT);
    unsigned* adjb  = (unsigned*)(smem2 + SMEM_ADJB);

    int tid  = threadIdx.x;
    int warp = tid >> 5, lane = tid & 31;
    int gid  = lane >> 2, tig = lane & 3;
    int hh   = warp;                      // warp == head
    int i0   = blockIdx.y * ITILE;
    int chunk = blockIdx.x;
    int jstart = chunk * JCHUNK;

    // hoisted per-row params (rows fixed per thread)
    float nsr[4][2], Pr[4][2], Rr[4][2];
#pragma unroll
    for (int mt = 0; mt < 4; mt++)
#pragma unroll
        for (int rh = 0; rh < 2; rh++) {
            int r = i0 + mt * 16 + rh * 8 + gid;
            nsr[mt][rh] = nsrc_g[hh * N_NODES + r];
            Pr[mt][rh]  = Pg[hh * N_NODES + r];
            Rr[mt][rh]  = Rg[hh * N_NODES + r];
        }

    float c[4][4][4];
#pragma unroll
    for (int mt = 0; mt < 4; mt++)
#pragma unroll
        for (int nt = 0; nt < 4; nt++)
#pragma unroll
            for (int u = 0; u < 4; u++) c[mt][nt][u] = 0.f;
    float z[4][2] = {};

    for (int jt = 0; jt < JCHUNK; jt += JT) {
        int j0 = jstart + jt;
        __syncthreads();
        // ---- stage adjacency as bitmask (coalesced LDG + ballot) ----
#pragma unroll 4
        for (int it = 0; it < 32; it++) {
            int ck = it * 8 + warp;                 // 0..255 : (row, word)
            int r = ck >> 2, cw = ck & 3;
            int v = adj[(size_t)(i0 + r) * N_NODES + j0 + cw * 32 + lane];
            unsigned b = __ballot_sync(0xffffffffu, v != 0);
            if (lane == 0) adjb[r * 4 + cw] = b;
        }
        // ---- stage jpack (s_dst, q, t) ----
        for (int idx = tid; idx < 8 * 128; idx += 256) {
            int h2 = idx >> 7, jj = idx & 127;
            jpack[idx] = jvec_g[h2 * N_NODES + j0 + jj];
        }
        // ---- stage g fp16 transposed tiles (8B units) ----
        for (int idx = tid; idx < 256 * 32; idx += 256) {
            int hf = idx >> 5, j4 = idx & 31;
            const int2* src = (const int2*)(&g_h_t[(size_t)hf * N_NODES + j0]);
            int2 v = src[j4];
            *(int2*)(&gTs[hf * 136 + j4 * 4]) = v;
        }
        __syncthreads();

#pragma unroll
        for (int ks = 0; ks < 8; ks++) {
            // B fragments from smem (conflict-free: stride 136 halves)
            unsigned bf[4][2];
#pragma unroll
            for (int nt = 0; nt < 4; nt++) {
                const unsigned* bp = (const unsigned*)gTs;     // half2 units
                int base = (hh * 32 + nt * 8 + gid) * 68 + ks * 8 + tig;
                bf[nt][0] = bp[base];
                bf[nt][1] = bp[base + 4];
            }
            int jb = hh * 128 + ks * 16 + tig * 2;
            float4 p0 = jpack[jb];
            float4 p1 = jpack[jb + 1];
            float4 p8 = jpack[jb + 8];
            float4 p9 = jpack[jb + 9];
            int wc = ks >> 1, sh = (ks & 1) * 16 + tig * 2;
#pragma unroll
            for (int mt = 0; mt < 4; mt++) {
                unsigned bw0 = adjb[(mt * 16 + gid) * 4 + wc] >> sh;
                unsigned bw1 = adjb[(mt * 16 + gid + 8) * 4 + wc] >> sh;

                float w00 = wcalc(p0, nsr[mt][0], Pr[mt][0], Rr[mt][0], bw0 & 1u);
                float w01 = wcalc(p1, nsr[mt][0], Pr[mt][0], Rr[mt][0], (bw0 >> 1) & 1u);
                float w08 = wcalc(p8, nsr[mt][0], Pr[mt][0], Rr[mt][0], (bw0 >> 8) & 1u);
                float w09 = wcalc(p9, nsr[mt][0], Pr[mt][0], Rr[mt][0], (bw0 >> 9) & 1u);
                float w10 = wcalc(p0, nsr[mt][1], Pr[mt][1], Rr[mt][1], bw1 & 1u);
                float w11 = wcalc(p1, nsr[mt][1], Pr[mt][1], Rr[mt][1], (bw1 >> 1) & 1u);
                float w18 = wcalc(p8, nsr[mt][1], Pr[mt][1], Rr[mt][1], (bw1 >> 8) & 1u);
                float w19 = wcalc(p9, nsr[mt][1], Pr[mt][1], Rr[mt][1], (bw1 >> 9) & 1u);

                z[mt][0] += (w00 + w01) + (w08 + w09);
                z[mt][1] += (w10 + w11) + (w18 + w19);

                unsigned a0 = pack2(w00, w01);
                unsigned a1 = pack2(w10, w11);
                unsigned a2 = pack2(w08, w09);
                unsigned a3 = pack2(w18, w19);
#pragma unroll
                for (int nt = 0; nt < 4; nt++)
                    mma16816(c[mt][nt], a0, a1, a2, a3, bf[nt][0], bf[nt][1]);
            }
        }
    }

    // ---- epilogue: numerator partials ----
#pragma unroll
    for (int mt = 0; mt < 4; mt++)
#pragma unroll
        for (int nt = 0; nt < 4; nt++) {
            int r0 = i0 + mt * 16 + gid;
            int col = hh * 32 + nt * 8 + tig * 2;
            float2 v0 = make_float2(c[mt][nt][0], c[mt][nt][1]);
            float2 v1 = make_float2(c[mt][nt][2], c[mt][nt][3]);
            *(float2*)(&num_part[chunk][r0][col])     = v0;
            *(float2*)(&num_part[chunk][r0 + 8][col]) = v1;
        }
    // ---- Z partials: reduce over quad (lanes sharing a row) ----
#pragma unroll
    for (int mt = 0; mt < 4; mt++)
#pragma unroll
        for (int rh = 0; rh < 2; rh++) {
            float v = z[mt][rh];
            v += __shfl_xor_sync(0xffffffffu, v, 1);
            v += __shfl_xor_sync(0xffffffffu, v, 2);
            if (tig == 0)
                z_part[chunk][hh][i0 + mt * 16 + rh * 8 + gid] = v;
        }
}

// ---------------- kernel 3: combine partials + divide ----------------
__global__ __launch_bounds__(256) void finalize(float* __restrict__ out) {
    int i = blockIdx.x, t = threadIdx.x;
    int hh = t >> 5;
    float num = 0.f, zz = 0.f;
#pragma unroll
    for (int ch = 0; ch < NCHUNK; ch++) {
        num += num_part[ch][i][t];
        zz  += z_part[ch][hh][i];
    }
    out[(size_t)i * OUTF + t] = num / zz;
}

// ---------------- launcher ----------------
extern "C" void kernel_launch(void* const* d_in, const int* in_sizes, int n_in,
                              void* d_out, int out_size) {
    const float* h   = (const float*)d_in[0];
    const int*   adj = (const int*)d_in[1];
    const float* W   = (const float*)d_in[2];
    const float* a   = (const float*)d_in[3];
    float* out = (float*)d_out;

    cudaFuncSetAttribute(attn_agg, cudaFuncAttributeMaxDynamicSharedMemorySize, SMEM2_SZ);

    gemm_g<<<dim3(4, 64), 256>>>(h, W);
    node_stats<<<512, 256>>>(a);
    attn_agg<<<dim3(NCHUNK, 64), 256, SMEM2_SZ>>>(adj);
    finalize<<<N_NODES, 256>>>(out);
}

// round 3
// speedup vs baseline: 1.7084x; 1.7084x over previous
#include <cuda_runtime.h>
#include <cuda_fp16.h>

#define N_NODES 4096
#define IN_F    256
#define HEADS   8
#define HID     32
#define OUTF    256
#define NCHUNK  2
#define JT      128
#define ITILE   64
#define JCHUNK  (N_NODES / NCHUNK)
#define NTILES  (JCHUNK / JT)

// ---------------- device scratch ----------------
__device__ __align__(16) float    g_f32[N_NODES * OUTF];
__device__ __align__(16) __half   g_h_t[OUTF * N_NODES];     // [h*32+f][n] fp16
__device__ __align__(16) float    nsrc_g[HEADS * N_NODES];
__device__ __align__(16) float    Pg[HEADS * N_NODES];
__device__ __align__(16) float    Rg[HEADS * N_NODES];
__device__ __align__(16) float4   jvec_g[HEADS * N_NODES];   // (s_dst, exp(s_dst), exp(.2 s_dst), 0)
__device__ __align__(16) unsigned adj_bits[N_NODES * (N_NODES / 32)];  // 2 MB bitmask
__device__ __align__(16) float    num_part[NCHUNK][N_NODES][OUTF];
__device__ __align__(16) float    z_part[NCHUNK][HEADS][N_NODES];

// ---------------- kernel 0: adjacency -> bitmask ----------------
__global__ __launch_bounds__(256) void adj_to_bits(const int* __restrict__ adj) {
    int warp = threadIdx.x >> 5, lane = threadIdx.x & 31;
    int gw = blockIdx.x * 8 + warp;          // 16384 warps
    int i = gw >> 2, wbase = (gw & 3) * 32;  // 32 words per warp
#pragma unroll 8
    for (int k = 0; k < 32; k++) {
        int v = adj[(size_t)i * N_NODES + (wbase + k) * 32 + lane];
        unsigned b = __ballot_sync(0xffffffffu, v != 0);
        if (lane == 0) adj_bits[i * 128 + wbase + k] = b;
    }
}

// ---------------- kernel 1: g = h @ W ----------------
__global__ __launch_bounds__(256) void gemm_g(const float* __restrict__ h,
                                              const float* __restrict__ W) {
    __shared__ float As[16][65];
    __shared__ float Bs[16][65];
    int tx = threadIdx.x & 15, ty = threadIdx.x >> 4;
    int i0 = blockIdx.y * 64, n0 = blockIdx.x * 64;
    float acc[4][4] = {};
    for (int k0 = 0; k0 < IN_F; k0 += 16) {
        for (int idx = threadIdx.x; idx < 64 * 16; idx += 256) {
            int r = idx >> 4, kk = idx & 15;
            As[kk][r] = h[(size_t)(i0 + r) * IN_F + k0 + kk];
        }
        for (int idx = threadIdx.x; idx < 16 * 64; idx += 256) {
            int kk = idx >> 6, c = idx & 63;
            Bs[kk][c] = W[(size_t)(k0 + kk) * OUTF + n0 + c];
        }
        __syncthreads();
#pragma unroll
        for (int kk = 0; kk < 16; kk++) {
            float av[4], bv[4];
#pragma unroll
            for (int u = 0; u < 4; u++) av[u] = As[kk][ty * 4 + u];
#pragma unroll
            for (int v = 0; v < 4; v++) bv[v] = Bs[kk][tx * 4 + v];
#pragma unroll
            for (int u = 0; u < 4; u++)
#pragma unroll
                for (int v = 0; v < 4; v++) acc[u][v] += av[u] * bv[v];
        }
        __syncthreads();
    }
#pragma unroll
    for (int u = 0; u < 4; u++)
#pragma unroll
        for (int v = 0; v < 4; v++)
            g_f32[(size_t)(i0 + ty * 4 + u) * OUTF + n0 + tx * 4 + v] = acc[u][v];
}

// ---------------- kernel 1b: node stats + fp16 transpose ----------------
__global__ __launch_bounds__(256) void node_stats(const float* __restrict__ a) {
    int warp = threadIdx.x >> 5, lane = threadIdx.x & 31;
    int n = blockIdx.x * 8 + warp;
    float gv[8];
#pragma unroll
    for (int c = 0; c < 8; c++) gv[c] = g_f32[(size_t)n * OUTF + c * 32 + lane];
    float as = a[lane], ad = a[32 + lane];
#pragma unroll
    for (int hh = 0; hh < 8; hh++) {
        float vs = gv[hh] * as, vd = gv[hh] * ad;
#pragma unroll
        for (int o = 16; o; o >>= 1) {
            vs += __shfl_xor_sync(0xffffffffu, vs, o);
            vd += __shfl_xor_sync(0xffffffffu, vd, o);
        }
        if (lane == 0) {
            nsrc_g[hh * N_NODES + n] = -vs;
            Pg[hh * N_NODES + n]     = expf(vs);
            Rg[hh * N_NODES + n]     = expf(0.2f * vs);
            jvec_g[hh * N_NODES + n] = make_float4(vd, expf(vd), expf(0.2f * vd), 0.f);
        }
        g_h_t[(size_t)(hh * 32 + lane) * N_NODES + n] = __float2half(gv[hh]);
    }
}

// ---------------- kernel 2: fused masked-softmax aggregation ----------------
__device__ __forceinline__ unsigned pack2(float lo, float hi) {
    __half2 hx = __floats2half2_rn(lo, hi);
    return *reinterpret_cast<unsigned*>(&hx);
}

__device__ __forceinline__ void mma16816(float* c, unsigned a0, unsigned a1,
                                         unsigned a2, unsigned a3,
                                         unsigned b0, unsigned b1) {
    asm volatile(
        "mma.sync.aligned.m16n8k16.row.col.f32.f16.f16.f32 "
        "{%0,%1,%2,%3}, {%4,%5,%6,%7}, {%8,%9}, {%0,%1,%2,%3};"
        : "+f"(c[0]), "+f"(c[1]), "+f"(c[2]), "+f"(c[3])
        : "r"(a0), "r"(a1), "r"(a2), "r"(a3), "r"(b0), "r"(b1));
}

__device__ __forceinline__ float wcalc(const float4& p, float ns, float Pv, float Rv,
                                       unsigned bit) {
    float v = (p.x >= ns) ? Pv * p.y : Rv * p.z;
    return bit ? v : 0.f;
}

__device__ __forceinline__ void cp_async4(unsigned dst, const void* src) {
    asm volatile("cp.async.ca.shared.global [%0], [%1], 4;" :: "r"(dst), "l"(src));
}
__device__ __forceinline__ void cp_async8(unsigned dst, const void* src) {
    asm volatile("cp.async.ca.shared.global [%0], [%1], 8;" :: "r"(dst), "l"(src));
}
__device__ __forceinline__ void cp_async16(unsigned dst, const void* src) {
    asm volatile("cp.async.cg.shared.global [%0], [%1], 16;" :: "r"(dst), "l"(src));
}
__device__ __forceinline__ void cp_commit() {
    asm volatile("cp.async.commit_group;" ::: "memory");
}
__device__ __forceinline__ void cp_wait0() {
    asm volatile("cp.async.wait_group 0;" ::: "memory");
}

// smem per buffer: jpack 16384 B, gTs 69632 B, adjb 1024 B  => 87040 * 2 = 174080 B
#define BUF_SZ     87040
#define OFF_JPACK  0
#define OFF_GT     16384
#define OFF_ADJB   (16384 + 69632)
#define SMEM2_SZ   (2 * BUF_SZ)

extern __shared__ char smem2[];

__global__ __launch_bounds__(512, 1) void attn_agg() {
    int tid  = threadIdx.x;
    int warp = tid >> 5, lane = tid & 31;
    int gid  = lane >> 2, tig = lane & 3;
    int hh   = warp & 7;          // head
    int half = warp >> 3;         // mt-half: handles mtg = half*2 + {0,1}
    int i0   = blockIdx.y * ITILE;
    int chunk = blockIdx.x;
    int jstart = chunk * JCHUNK;

    unsigned sbase = (unsigned)__cvta_generic_to_shared(smem2);

    // ---- staging lambda-ish: issue cp.async for tile t into buffer (t&1) ----
    // gTs: 8192 x 8B, jpack: 1024 x 16B, adjb: 256 x 4B
    auto stage = [&](int t) {
        int j0 = jstart + t * JT;
        unsigned b = sbase + (t & 1) * BUF_SZ;
#pragma unroll
        for (int q = 0; q < 16; q++) {            // 8192 / 512
            int idx = q * 512 + tid;
            int hf = idx >> 5, j4 = idx & 31;
            cp_async8(b + OFF_GT + (hf * 136 + j4 * 4) * 2,
                      &g_h_t[(size_t)hf * N_NODES + j0 + j4 * 4]);
        }
#pragma unroll
        for (int q = 0; q < 2; q++) {             // 1024 / 512
            int idx = q * 512 + tid;
            int h2 = idx >> 7, jj = idx & 127;
            cp_async16(b + OFF_JPACK + idx * 16,
                       &jvec_g[h2 * N_NODES + j0 + jj]);
        }
        if (tid < 256) {
            int r = tid >> 2, cw = tid & 3;
            cp_async4(b + OFF_ADJB + tid * 4,
                      &adj_bits[(i0 + r) * 128 + (j0 >> 5) + cw]);
        }
        cp_commit();
    };

    // hoisted per-row params
    float nsr[2][2], Pr[2][2], Rr[2][2];
#pragma unroll
    for (int mti = 0; mti < 2; mti++)
#pragma unroll
        for (int rh = 0; rh < 2; rh++) {
            int r = i0 + (half * 2 + mti) * 16 + rh * 8 + gid;
            nsr[mti][rh] = nsrc_g[hh * N_NODES + r];
            Pr[mti][rh]  = Pg[hh * N_NODES + r];
            Rr[mti][rh]  = Rg[hh * N_NODES + r];
        }

    float c[2][4][4];
#pragma unroll
    for (int mti = 0; mti < 2; mti++)
#pragma unroll
        for (int nt = 0; nt < 4; nt++)
#pragma unroll
            for (int u = 0; u < 4; u++) c[mti][nt][u] = 0.f;
    float z[2][2] = {};

    stage(0);

    for (int t = 0; t < NTILES; t++) {
        cp_wait0();
        __syncthreads();
        if (t + 1 < NTILES) stage(t + 1);

        const char* buf = smem2 + (t & 1) * BUF_SZ;
        const float4*   jpack = (const float4*)(buf + OFF_JPACK);
        const unsigned* bp    = (const unsigned*)(buf + OFF_GT);   // half2 units
        const unsigned* adjb  = (const unsigned*)(buf + OFF_ADJB);

#pragma unroll
        for (int ks = 0; ks < 8; ks++) {
            unsigned bf[4][2];
#pragma unroll
            for (int nt = 0; nt < 4; nt++) {
                int base = (hh * 32 + nt * 8 + gid) * 68 + ks * 8 + tig;
                bf[nt][0] = bp[base];
                bf[nt][1] = bp[base + 4];
            }
            int jb = hh * 128 + ks * 16 + tig * 2;
            float4 p0 = jpack[jb];
            float4 p1 = jpack[jb + 1];
            float4 p8 = jpack[jb + 8];
            float4 p9 = jpack[jb + 9];
            int wc = ks >> 1, sh = (ks & 1) * 16 + tig * 2;
#pragma unroll
            for (int mti = 0; mti < 2; mti++) {
                int mtg = half * 2 + mti;
                unsigned bw0 = adjb[(mtg * 16 + gid) * 4 + wc] >> sh;
                unsigned bw1 = adjb[(mtg * 16 + gid + 8) * 4 + wc] >> sh;

                float w00 = wcalc(p0, nsr[mti][0], Pr[mti][0], Rr[mti][0], bw0 & 1u);
                float w01 = wcalc(p1, nsr[mti][0], Pr[mti][0], Rr[mti][0], (bw0 >> 1) & 1u);
                float w08 = wcalc(p8, nsr[mti][0], Pr[mti][0], Rr[mti][0], (bw0 >> 8) & 1u);
                float w09 = wcalc(p9, nsr[mti][0], Pr[mti][0], Rr[mti][0], (bw0 >> 9) & 1u);
                float w10 = wcalc(p0, nsr[mti][1], Pr[mti][1], Rr[mti][1], bw1 & 1u);
                float w11 = wcalc(p1, nsr[mti][1], Pr[mti][1], Rr[mti][1], (bw1 >> 1) & 1u);
                float w18 = wcalc(p8, nsr[mti][1], Pr[mti][1], Rr[mti][1], (bw1 >> 8) & 1u);
                float w19 = wcalc(p9, nsr[mti][1], Pr[mti][1], Rr[mti][1], (bw1 >> 9) & 1u);

                z[mti][0] += (w00 + w01) + (w08 + w09);
                z[mti][1] += (w10 + w11) + (w18 + w19);

                unsigned a0 = pack2(w00, w01);
                unsigned a1 = pack2(w10, w11);
                unsigned a2 = pack2(w08, w09);
                unsigned a3 = pack2(w18, w19);
#pragma unroll
                for (int nt = 0; nt < 4; nt++)
                    mma16816(c[mti][nt], a0, a1, a2, a3, bf[nt][0], bf[nt][1]);
            }
        }
        __syncthreads();   // compute done before next wait re-syncs buffers
    }

    // ---- epilogue ----
#pragma unroll
    for (int mti = 0; mti < 2; mti++)
#pragma unroll
        for (int nt = 0; nt < 4; nt++) {
            int r0 = i0 + (half * 2 + mti) * 16 + gid;
            int col = hh * 32 + nt * 8 + tig * 2;
            float2 v0 = make_float2(c[mti][nt][0], c[mti][nt][1]);
            float2 v1 = make_float2(c[mti][nt][2], c[mti][nt][3]);
            *(float2*)(&num_part[chunk][r0][col])     = v0;
            *(float2*)(&num_part[chunk][r0 + 8][col]) = v1;
        }
#pragma unroll
    for (int mti = 0; mti < 2; mti++)
#pragma unroll
        for (int rh = 0; rh < 2; rh++) {
            float v = z[mti][rh];
            v += __shfl_xor_sync(0xffffffffu, v, 1);
            v += __shfl_xor_sync(0xffffffffu, v, 2);
            if (tig == 0)
                z_part[chunk][hh][i0 + (half * 2 + mti) * 16 + rh * 8 + gid] = v;
        }
}

// ---------------- kernel 3: combine + divide ----------------
__global__ __launch_bounds__(256) void finalize(float* __restrict__ out) {
    int i = blockIdx.x, t = threadIdx.x;
    int hh = t >> 5;
    float num = 0.f, zz = 0.f;
#pragma unroll
    for (int ch = 0; ch < NCHUNK; ch++) {
        num += num_part[ch][i][t];
        zz  += z_part[ch][hh][i];
    }
    out[(size_t)i * OUTF + t] = num / zz;
}

// ---------------- launcher ----------------
extern "C" void kernel_launch(void* const* d_in, const int* in_sizes, int n_in,
                              void* d_out, int out_size) {
    const float* h   = (const float*)d_in[0];
    const int*   adj = (const int*)d_in[1];
    const float* W   = (const float*)d_in[2];
    const float* a   = (const float*)d_in[3];
    float* out = (float*)d_out;

    cudaFuncSetAttribute(attn_agg, cudaFuncAttributeMaxDynamicSharedMemorySize, SMEM2_SZ);

    adj_to_bits<<<2048, 256>>>(adj);
    gemm_g<<<dim3(4, 64), 256>>>(h, W);
    node_stats<<<512, 256>>>(a);
    attn_agg<<<dim3(NCHUNK, 64), 512, SMEM2_SZ>>>();
    finalize<<<N_NODES, 256>>>(out);
}

// round 4
// speedup vs baseline: 2.3130x; 1.3539x over previous
#include <cuda_runtime.h>
#include <cuda_fp16.h>

#define N_NODES 4096
#define HEADS   8
#define OUTF    256
#define NCHUNK  2
#define JT      128
#define ITILE   64
#define JCHUNK  (N_NODES / NCHUNK)
#define NTILES  (JCHUNK / JT)

// ---------------- device scratch ----------------
__device__ __align__(16) float    g_f32[N_NODES * OUTF];
__device__ __align__(16) __half   g_h_t[OUTF * N_NODES];       // [h*32+f][n] fp16
__device__ __align__(16) __half2  PR_g[HEADS * N_NODES];       // (exp(s_src), exp(.2 s_src))
__device__ __align__(16) __half   qg[HEADS * N_NODES];         // exp(s_dst)
__device__ __align__(16) __half   tg[HEADS * N_NODES];         // exp(.2 s_dst)
__device__ __align__(16) unsigned adj_bits[N_NODES * (N_NODES / 32)];
__device__ __align__(16) float    num_part[NCHUNK][N_NODES][OUTF];
__device__ __align__(16) float    z_part[NCHUNK][HEADS][N_NODES];

// ---------------- kernel 0: adjacency -> bitmask ----------------
__global__ __launch_bounds__(256) void adj_to_bits(const int* __restrict__ adj) {
    int warp = threadIdx.x >> 5, lane = threadIdx.x & 31;
    int gw = blockIdx.x * 8 + warp;
    int i = gw >> 2, wbase = (gw & 3) * 32;
#pragma unroll 8
    for (int k = 0; k < 32; k++) {
        int v = adj[(size_t)i * N_NODES + (wbase + k) * 32 + lane];
        unsigned b = __ballot_sync(0xffffffffu, v != 0);
        if (lane == 0) adj_bits[i * 128 + wbase + k] = b;
    }
}

// ---------------- kernel 1: g = h @ W (fp32, 128x64 tile, 8x4 micro) ----------------
__global__ __launch_bounds__(256) void gemm_g(const float* __restrict__ h,
                                              const float* __restrict__ W) {
    __shared__ float As[16][132];   // [kk][m], m=128
    __shared__ float Bs[16][68];    // [kk][n], n=64
    int tid = threadIdx.x;
    int tx = tid & 15, ty = tid >> 4;           // tx: n-quad, ty: m-oct
    int i0 = blockIdx.y * 128, n0 = blockIdx.x * 64;
    float acc[8][4] = {};
    for (int k0 = 0; k0 < 256; k0 += 16) {
#pragma unroll
        for (int q = 0; q < 2; q++) {           // A: 128x16 = 512 float4
            int idx = q * 256 + tid;
            int m = idx >> 2, kq = idx & 3;
            float4 v = *(const float4*)&h[(size_t)(i0 + m) * 256 + k0 + kq * 4];
            As[kq * 4 + 0][m] = v.x; As[kq * 4 + 1][m] = v.y;
            As[kq * 4 + 2][m] = v.z; As[kq * 4 + 3][m] = v.w;
        }
        {                                       // B: 16x64 = 256 float4
            int kk = tid >> 4, n4 = tid & 15;
            float4 v = *(const float4*)&W[(size_t)(k0 + kk) * 256 + n0 + n4 * 4];
            *(float4*)&Bs[kk][n4 * 4] = v;
        }
        __syncthreads();
#pragma unroll
        for (int kk = 0; kk < 16; kk++) {
            float av[8], bv[4];
#pragma unroll
            for (int u = 0; u < 8; u++) av[u] = As[kk][ty * 8 + u];
#pragma unroll
            for (int v = 0; v < 4; v++) bv[v] = Bs[kk][tx * 4 + v];
#pragma unroll
            for (int u = 0; u < 8; u++)
#pragma unroll
                for (int v = 0; v < 4; v++) acc[u][v] += av[u] * bv[v];
        }
        __syncthreads();
    }
#pragma unroll
    for (int u = 0; u < 8; u++)
#pragma unroll
        for (int v = 0; v < 4; v++)
            g_f32[(size_t)(i0 + ty * 8 + u) * 256 + n0 + tx * 4 + v] = acc[u][v];
}

// ---------------- kernel 1b: node stats + fp16 transpose ----------------
__global__ __launch_bounds__(256) void node_stats(const float* __restrict__ a) {
    int warp = threadIdx.x >> 5, lane = threadIdx.x & 31;
    int n = blockIdx.x * 8 + warp;
    float gv[8];
#pragma unroll
    for (int c = 0; c < 8; c++) gv[c] = g_f32[(size_t)n * OUTF + c * 32 + lane];
    float as = a[lane], ad = a[32 + lane];
#pragma unroll
    for (int hh = 0; hh < 8; hh++) {
        float vs = gv[hh] * as, vd = gv[hh] * ad;
#pragma unroll
        for (int o = 16; o; o >>= 1) {
            vs += __shfl_xor_sync(0xffffffffu, vs, o);
            vd += __shfl_xor_sync(0xffffffffu, vd, o);
        }
        if (lane == 0) {
            PR_g[hh * N_NODES + n] = __floats2half2_rn(expf(vs), expf(0.2f * vs));
            qg[hh * N_NODES + n]   = __float2half(expf(vd));
            tg[hh * N_NODES + n]   = __float2half(expf(0.2f * vd));
        }
        g_h_t[(size_t)(hh * 32 + lane) * N_NODES + n] = __float2half(gv[hh]);
    }
}

// ---------------- kernel 2 helpers ----------------
__device__ __forceinline__ void mma16816(float* c, unsigned a0, unsigned a1,
                                         unsigned a2, unsigned a3,
                                         unsigned b0, unsigned b1) {
    asm volatile(
        "mma.sync.aligned.m16n8k16.row.col.f32.f16.f16.f32 "
        "{%0,%1,%2,%3}, {%4,%5,%6,%7}, {%8,%9}, {%0,%1,%2,%3};"
        : "+f"(c[0]), "+f"(c[1]), "+f"(c[2]), "+f"(c[3])
        : "r"(a0), "r"(a1), "r"(a2), "r"(a3), "r"(b0), "r"(b1));
}

__device__ __forceinline__ unsigned expand2(unsigned b) {
    // 2 adjacency bits -> 2 half-lane AND masks
    return (b & 1u) * 0xFFFFu + (b & 2u) * 0x7FFF8000u;
}

__device__ __forceinline__ unsigned wpair(__half2 P2, __half2 R2,
                                          unsigned q2, unsigned t2, unsigned m) {
    __half2 qq = *(__half2*)&q2, tt = *(__half2*)&t2;
    __half2 u = __hmax2(__hmul2(P2, qq), __hmul2(R2, tt));
    return (*(unsigned*)&u) & m;
}

__device__ __forceinline__ void cp_async4(unsigned dst, const void* src) {
    asm volatile("cp.async.ca.shared.global [%0], [%1], 4;" :: "r"(dst), "l"(src));
}
__device__ __forceinline__ void cp_async8(unsigned dst, const void* src) {
    asm volatile("cp.async.ca.shared.global [%0], [%1], 8;" :: "r"(dst), "l"(src));
}
__device__ __forceinline__ void cp_commit() {
    asm volatile("cp.async.commit_group;" ::: "memory");
}
__device__ __forceinline__ void cp_wait0() {
    asm volatile("cp.async.wait_group 0;" ::: "memory");
}

// smem/buffer: gTs 69632 + jq 2048 + jt 2048 + adjb 1024 = 74752; x2 = 149504
#define OFF_GT     0
#define OFF_JQ     69632
#define OFF_JT     71680
#define OFF_ADJB   73728
#define BUF_SZ     74752
#define SMEM2_SZ   (2 * BUF_SZ)

extern __shared__ char smem2[];

__global__ __launch_bounds__(512, 1) void attn_agg() {
    int tid  = threadIdx.x;
    int warp = tid >> 5, lane = tid & 31;
    int gid  = lane >> 2, tig = lane & 3;
    int hh   = warp & 7;
    int mq   = warp >> 3;          // covers mtg = mq*2 + {0,1}
    int i0   = blockIdx.y * ITILE;
    int chunk = blockIdx.x;
    int jstart = chunk * JCHUNK;

    unsigned sbase = (unsigned)__cvta_generic_to_shared(smem2);

    auto stage = [&](int t) {
        int j0 = jstart + t * JT;
        unsigned b = sbase + (t & 1) * BUF_SZ;
#pragma unroll
        for (int q = 0; q < 16; q++) {            // gTs: 8192 x 8B
            int idx = q * 512 + tid;
            int hf = idx >> 5, j4 = idx & 31;
            cp_async8(b + OFF_GT + (hf * 136 + j4 * 4) * 2,
                      &g_h_t[(size_t)hf * N_NODES + j0 + j4 * 4]);
        }
        {                                         // jq, jt: 512 x 4B each
            int h2 = tid >> 6, o = tid & 63;
            cp_async4(b + OFF_JQ + tid * 4, &qg[h2 * N_NODES + j0 + o * 2]);
            cp_async4(b + OFF_JT + tid * 4, &tg[h2 * N_NODES + j0 + o * 2]);
        }
        if (tid < 256) {                          // adjb: 64 rows x 4 words
            int r = tid >> 2, cw = tid & 3;
            cp_async4(b + OFF_ADJB + tid * 4,
                      &adj_bits[(i0 + r) * 128 + (j0 >> 5) + cw]);
        }
        cp_commit();
    };

    // per-row broadcast params
    __half2 P2[2][2], R2[2][2];
#pragma unroll
    for (int mti = 0; mti < 2; mti++)
#pragma unroll
        for (int rh = 0; rh < 2; rh++) {
            int r = i0 + (mq * 2 + mti) * 16 + rh * 8 + gid;
            __half2 pr = PR_g[hh * N_NODES + r];
            P2[mti][rh] = __half2half2(__low2half(pr));
            R2[mti][rh] = __half2half2(__high2half(pr));
        }

    float c[2][4][4];
    float cz[2][4];
#pragma unroll
    for (int mti = 0; mti < 2; mti++) {
#pragma unroll
        for (int nt = 0; nt < 4; nt++)
#pragma unroll
            for (int u = 0; u < 4; u++) c[mti][nt][u] = 0.f;
#pragma unroll
        for (int u = 0; u < 4; u++) cz[mti][u] = 0.f;
    }

    const unsigned ONES = 0x3C003C00u;   // half2(1,1)

    stage(0);

    for (int t = 0; t < NTILES; t++) {
        cp_wait0();
        __syncthreads();
        if (t + 1 < NTILES) stage(t + 1);

        const char* buf = smem2 + (t & 1) * BUF_SZ;
        const unsigned* bp   = (const unsigned*)(buf + OFF_GT);    // half2 units
        const __half*   jq   = (const __half*)(buf + OFF_JQ);
        const __half*   jt   = (const __half*)(buf + OFF_JT);
        const unsigned* adjb = (const unsigned*)(buf + OFF_ADJB);

#pragma unroll
        for (int ks = 0; ks < 8; ks++) {
            unsigned bf[4][2];
#pragma unroll
            for (int nt = 0; nt < 4; nt++) {
                int base = (hh * 32 + nt * 8 + gid) * 68 + ks * 8 + tig;
                bf[nt][0] = bp[base];
                bf[nt][1] = bp[base + 4];
            }
            int jo = hh * 128 + ks * 16 + tig * 2;
            unsigned qlo = *(const unsigned*)(jq + jo);
            unsigned qhi = *(const unsigned*)(jq + jo + 8);
            unsigned tlo = *(const unsigned*)(jt + jo);
            unsigned thi = *(const unsigned*)(jt + jo + 8);
            int wc = ks >> 1, sh = (ks & 1) * 16 + tig * 2;
#pragma unroll
            for (int mti = 0; mti < 2; mti++) {
                int mtg = mq * 2 + mti;
                unsigned bw0 = adjb[(mtg * 16 + gid) * 4 + wc] >> sh;
                unsigned bw1 = adjb[(mtg * 16 + gid + 8) * 4 + wc] >> sh;

                unsigned m00 = expand2(bw0 & 3u);
                unsigned m10 = expand2(bw1 & 3u);
                unsigned m01 = expand2((bw0 >> 8) & 3u);
                unsigned m11 = expand2((bw1 >> 8) & 3u);

                unsigned a0 = wpair(P2[mti][0], R2[mti][0], qlo, tlo, m00);
                unsigned a1 = wpair(P2[mti][1], R2[mti][1], qlo, tlo, m10);
                unsigned a2 = wpair(P2[mti][0], R2[mti][0], qhi, thi, m01);
                unsigned a3 = wpair(P2[mti][1], R2[mti][1], qhi, thi, m11);

#pragma unroll
                for (int nt = 0; nt < 4; nt++)
                    mma16816(c[mti][nt], a0, a1, a2, a3, bf[nt][0], bf[nt][1]);
                mma16816(cz[mti], a0, a1, a2, a3, ONES, ONES);   // z row-sums
            }
        }
        __syncthreads();
    }

    // ---- epilogue ----
#pragma unroll
    for (int mti = 0; mti < 2; mti++)
#pragma unroll
        for (int nt = 0; nt < 4; nt++) {
            int r0 = i0 + (mq * 2 + mti) * 16 + gid;
            int col = hh * 32 + nt * 8 + tig * 2;
            float2 v0 = make_float2(c[mti][nt][0], c[mti][nt][1]);
            float2 v1 = make_float2(c[mti][nt][2], c[mti][nt][3]);
            *(float2*)(&num_part[chunk][r0][col])     = v0;
            *(float2*)(&num_part[chunk][r0 + 8][col]) = v1;
        }
    if (tig == 0) {
#pragma unroll
        for (int mti = 0; mti < 2; mti++) {
            int r0 = i0 + (mq * 2 + mti) * 16 + gid;
            z_part[chunk][hh][r0]     = cz[mti][0];
            z_part[chunk][hh][r0 + 8] = cz[mti][2];
        }
    }
}

// ---------------- kernel 3: combine + divide ----------------
__global__ __launch_bounds__(256) void finalize(float* __restrict__ out) {
    int i = blockIdx.x, t = threadIdx.x;
    int hh = t >> 5;
    float num = 0.f, zz = 0.f;
#pragma unroll
    for (int ch = 0; ch < NCHUNK; ch++) {
        num += num_part[ch][i][t];
        zz  += z_part[ch][hh][i];
    }
    out[(size_t)i * OUTF + t] = num / zz;
}

// ---------------- launcher ----------------
extern "C" void kernel_launch(void* const* d_in, const int* in_sizes, int n_in,
                              void* d_out, int out_size) {
    const float* h   = (const float*)d_in[0];
    const int*   adj = (const int*)d_in[1];
    const float* W   = (const float*)d_in[2];
    const float* a   = (const float*)d_in[3];
    float* out = (float*)d_out;

    cudaFuncSetAttribute(attn_agg, cudaFuncAttributeMaxDynamicSharedMemorySize, SMEM2_SZ);

    adj_to_bits<<<2048, 256>>>(adj);
    gemm_g<<<dim3(4, 32), 256>>>(h, W);
    node_stats<<<512, 256>>>(a);
    attn_agg<<<dim3(NCHUNK, 64), 512, SMEM2_SZ>>>();
    finalize<<<N_NODES, 256>>>(out);
}

// round 6
// speedup vs baseline: 2.4840x; 1.0739x over previous
#include <cuda_runtime.h>
#include <cuda_fp16.h>

#define N_NODES 4096
#define HEADS   8
#define OUTF    256
#define NCHUNK  2
#define JT      128
#define ITILE   64
#define JCHUNK  (N_NODES / NCHUNK)
#define NTILES  (JCHUNK / JT)

// ---------------- device scratch ----------------
__device__ __align__(16) __half   g_h_t[OUTF * N_NODES];       // [h*32+f][n] fp16
__device__ __align__(16) float    Wa_g[256 * 16];              // [k][head + 8*dst]
__device__ __align__(16) __half2  PR_g[HEADS * N_NODES];       // (exp(s_src), exp(.2 s_src))
__device__ __align__(16) __half   qg[HEADS * N_NODES];         // exp(s_dst)
__device__ __align__(16) __half   tg[HEADS * N_NODES];         // exp(.2 s_dst)
__device__ __align__(16) unsigned adj_bits[N_NODES * (N_NODES / 32)];
__device__ __align__(16) float    num_part[NCHUNK][N_NODES][OUTF];
__device__ __align__(16) float    z_part[NCHUNK][HEADS][N_NODES];

// ---------------- kernel 0: adjacency -> bitmask ----------------
__global__ __launch_bounds__(256) void adj_to_bits(const int* __restrict__ adj) {
    int warp = threadIdx.x >> 5, lane = threadIdx.x & 31;
    int gw = blockIdx.x * 8 + warp;
    int i = gw >> 2, wbase = (gw & 3) * 32;
#pragma unroll 8
    for (int k = 0; k < 32; k++) {
        int v = adj[(size_t)i * N_NODES + (wbase + k) * 32 + lane];
        unsigned b = __ballot_sync(0xffffffffu, v != 0);
        if (lane == 0) adj_bits[i * 128 + wbase + k] = b;
    }
}

// ---------------- kernel A: Wa[k][c] = sum_f W[k, h*32+f] * a[dst*32+f] ----------------
__global__ __launch_bounds__(256) void compute_wa(const float* __restrict__ W,
                                                  const float* __restrict__ a) {
    int warp = threadIdx.x >> 5, lane = threadIdx.x & 31;
    int k = blockIdx.x * 8 + warp;
    float wrow[8];
#pragma unroll
    for (int hd = 0; hd < 8; hd++) wrow[hd] = W[(size_t)k * 256 + hd * 32 + lane];
    float asrc = a[lane], adst = a[32 + lane];
#pragma unroll
    for (int c = 0; c < 16; c++) {
        float v = wrow[c & 7] * ((c < 8) ? asrc : adst);
#pragma unroll
        for (int o = 16; o; o >>= 1) v += __shfl_xor_sync(0xffffffffu, v, o);
        if (lane == 0) Wa_g[k * 16 + c] = v;
    }
}

// ---------------- kernel B: node scores s = h @ Wa -> PR/q/t ----------------
__global__ __launch_bounds__(256) void node_stats2(const float* __restrict__ h) {
    __shared__ float sh_h[16][257];
    __shared__ float sh_wa[256][17];
    int tid = threadIdx.x;
    int n0 = blockIdx.x * 16;
#pragma unroll
    for (int q = 0; q < 16; q++) {
        int idx = q * 256 + tid;
        sh_h[idx >> 8][idx & 255] = h[(size_t)n0 * 256 + idx];
        sh_wa[idx >> 4][idx & 15] = Wa_g[idx];
    }
    __syncthreads();
    int nl = tid >> 4, c = tid & 15;
    float s = 0.f;
#pragma unroll 8
    for (int k = 0; k < 256; k++) s += sh_h[nl][k] * sh_wa[k][c];
    int n = n0 + nl;
    if (c < 8) {
        PR_g[c * N_NODES + n] = __floats2half2_rn(expf(s), expf(0.2f * s));
    } else {
        qg[(c - 8) * N_NODES + n] = __float2half(expf(s));
        tg[(c - 8) * N_NODES + n] = __float2half(expf(0.2f * s));
    }
}

// ---------------- kernel 1: g = h @ W -> fp16 transposed g_h_t ----------------
__global__ __launch_bounds__(256) void gemm_g(const float* __restrict__ h,
                                              const float* __restrict__ W) {
    __shared__ __align__(16) char smg[64 * 136 * 2];   // 17408 B, aliased
    float (*As)[132] = (float(*)[132])smg;             // 16x132 f32 = 8448
    float (*Bs)[68]  = (float(*)[68])(smg + 8448);     // 16x68  f32 = 4352
    __half (*tT)[136] = (__half(*)[136])smg;           // 64x136 f16 = 17408

    int tid = threadIdx.x;
    int tx = tid & 15, ty = tid >> 4;
    int i0 = blockIdx.y * 128, n0 = blockIdx.x * 64;
    float acc[8][4] = {};
    for (int k0 = 0; k0 < 256; k0 += 16) {
#pragma unroll
        for (int q = 0; q < 2; q++) {
            int idx = q * 256 + tid;
            int m = idx >> 2, kq = idx & 3;
            float4 v = *(const float4*)&h[(size_t)(i0 + m) * 256 + k0 + kq * 4];
            As[kq * 4 + 0][m] = v.x; As[kq * 4 + 1][m] = v.y;
            As[kq * 4 + 2][m] = v.z; As[kq * 4 + 3][m] = v.w;
        }
        {
            int kk = tid >> 4, n4 = tid & 15;
            float4 v = *(const float4*)&W[(size_t)(k0 + kk) * 256 + n0 + n4 * 4];
            *(float4*)&Bs[kk][n4 * 4] = v;
        }
        __syncthreads();
#pragma unroll
        for (int kk = 0; kk < 16; kk++) {
            float av[8], bv[4];
#pragma unroll
            for (int u = 0; u < 8; u++) av[u] = As[kk][ty * 8 + u];
#pragma unroll
            for (int v = 0; v < 4; v++) bv[v] = Bs[kk][tx * 4 + v];
#pragma unroll
            for (int u = 0; u < 8; u++)
#pragma unroll
                for (int v = 0; v < 4; v++) acc[u][v] += av[u] * bv[v];
        }
        __syncthreads();
    }
    // transpose to fp16 in smem, then coalesced global write
#pragma unroll
    for (int u = 0; u < 8; u++)
#pragma unroll
        for (int v = 0; v < 4; v++)
            tT[tx * 4 + v][ty * 8 + u] = __float2half(acc[u][v]);
    __syncthreads();
#pragma unroll
    for (int q = 0; q < 4; q++) {
        int idx = q * 256 + tid;
        int nl = idx >> 4, m4 = idx & 15;
        *(int4*)&g_h_t[(size_t)(n0 + nl) * N_NODES + i0 + m4 * 8] = *(int4*)&tT[nl][m4 * 8];
    }
}

// ---------------- kernel 2 helpers ----------------
__device__ __forceinline__ void mma16816(float* c, unsigned a0, unsigned a1,
                                         unsigned a2, unsigned a3,
                                         unsigned b0, unsigned b1) {
    asm volatile(
        "mma.sync.aligned.m16n8k16.row.col.f32.f16.f16.f32 "
        "{%0,%1,%2,%3}, {%4,%5,%6,%7}, {%8,%9}, {%0,%1,%2,%3};"
        : "+f"(c[0]), "+f"(c[1]), "+f"(c[2]), "+f"(c[3])
        : "r"(a0), "r"(a1), "r"(a2), "r"(a3), "r"(b0), "r"(b1));
}

__device__ __forceinline__ void ldsm_x4(unsigned* r, unsigned addr) {
    asm volatile(
        "ldmatrix.sync.aligned.m8n8.x4.shared.b16 {%0,%1,%2,%3}, [%4];"
        : "=r"(r[0]), "=r"(r[1]), "=r"(r[2]), "=r"(r[3]) : "r"(addr));
}

__device__ __forceinline__ unsigned expand2(unsigned b) {
    return (b & 1u) * 0xFFFFu + (b & 2u) * 0x7FFF8000u;
}

__device__ __forceinline__ unsigned wpair(__half2 P2, __half2 R2,
                                          unsigned q2, unsigned t2) {
    __half2 qq = *(__half2*)&q2, tt = *(__half2*)&t2;
    __half2 u = __hmax2(__hmul2(P2, qq), __hmul2(R2, tt));
    return *(unsigned*)&u;
}

__device__ __forceinline__ void cp_async4(unsigned dst, const void* src) {
    asm volatile("cp.async.ca.shared.global [%0], [%1], 4;" :: "r"(dst), "l"(src));
}
__device__ __forceinline__ void cp_async8(unsigned dst, const void* src) {
    asm volatile("cp.async.ca.shared.global [%0], [%1], 8;" :: "r"(dst), "l"(src));
}
__device__ __forceinline__ void cp_commit() {
    asm volatile("cp.async.commit_group;" ::: "memory");
}
__device__ __forceinline__ void cp_wait0() {
    asm volatile("cp.async.wait_group 0;" ::: "memory");
}

// buffer: gTs 69632 | jq 2048 | jt 2048 | adjb 1024 | masks 16384 = 91136 ; x2
#define OFF_GT     0
#define OFF_JQ     69632
#define OFF_JT     71680
#define OFF_ADJB   73728
#define OFF_MASK   74752
#define BUF_SZ     91136
#define SMEM2_SZ   (2 * BUF_SZ)

extern __shared__ char smem2[];

__global__ __launch_bounds__(1024, 1) void attn_agg() {
    int tid  = threadIdx.x;
    int warp = tid >> 5, lane = tid & 31;
    int gid  = lane >> 2, tig = lane & 3;
    int hh   = warp & 7;
    int mtg  = warp >> 3;          // 0..3, one m16 tile per warp
    int i0   = blockIdx.y * ITILE;
    int chunk = blockIdx.x;
    int jstart = chunk * JCHUNK;

    unsigned sbase = (unsigned)__cvta_generic_to_shared(smem2);

    auto stage = [&](int t) {
        int j0 = jstart + t * JT;
        unsigned b = sbase + (t & 1) * BUF_SZ;
#pragma unroll
        for (int q = 0; q < 8; q++) {             // gTs: 8192 x 8B
            int idx = q * 1024 + tid;
            int hf = idx >> 5, j4 = idx & 31;
            cp_async8(b + OFF_GT + (hf * 136 + j4 * 4) * 2,
                      &g_h_t[(size_t)hf * N_NODES + j0 + j4 * 4]);
        }
        if (tid < 512) {                          // jq, jt: 512 x 4B each
            int h2 = tid >> 6, o = tid & 63;
            cp_async4(b + OFF_JQ + tid * 4, &qg[h2 * N_NODES + j0 + o * 2]);
            cp_async4(b + OFF_JT + tid * 4, &tg[h2 * N_NODES + j0 + o * 2]);
        }
        if (tid < 256) {                          // adjb raw: 64 rows x 4 words
            int r = tid >> 2, cw = tid & 3;
            cp_async4(b + OFF_ADJB + tid * 4,
                      &adj_bits[(i0 + r) * 128 + (j0 >> 5) + cw]);
        }
        cp_commit();
    };

    // per-row broadcast params (2 rows per warp: gid, gid+8 within m16 tile)
    __half2 P2[2], R2[2];
#pragma unroll
    for (int rh = 0; rh < 2; rh++) {
        int r = i0 + mtg * 16 + rh * 8 + gid;
        __half2 pr = PR_g[hh * N_NODES + r];
        P2[rh] = __half2half2(__low2half(pr));
        R2[rh] = __half2half2(__high2half(pr));
    }

    // ldmatrix per-lane base byte-offsets within gTs
    int ntl = lane >> 4, hb = (lane >> 3) & 1, rowl = lane & 7;
    unsigned lds_off0 = ((hh * 32 + ntl * 8 + rowl) * 136 + hb * 8) * 2;
    unsigned lds_off1 = lds_off0 + 16 * 136 * 2;

    float c[4][4] = {};
    float cz[4] = {};
    const unsigned ONES = 0x3C003C00u;

    // mask-expansion indices for this thread (1024 groups, one each)
    int emtg = tid >> 8, eks = (tid >> 5) & 7, egid = (tid >> 2) & 7, etig = tid & 3;
    int ewc = eks >> 1, esh = (eks & 1) * 16 + etig * 2;

    stage(0);

    for (int t = 0; t < NTILES; t++) {
        cp_wait0();
        __syncthreads();
        if (t + 1 < NTILES) stage(t + 1);

        char* buf = smem2 + (t & 1) * BUF_SZ;
        {   // expand adjacency bits -> per-fragment AND masks (once per tile)
            const unsigned* adjb = (const unsigned*)(buf + OFF_ADJB);
            unsigned bw0 = adjb[(emtg * 16 + egid) * 4 + ewc] >> esh;
            unsigned bw1 = adjb[(emtg * 16 + egid + 8) * 4 + ewc] >> esh;
            uint4 m;
            m.x = expand2(bw0 & 3u);
            m.y = expand2(bw1 & 3u);
            m.z = expand2((bw0 >> 8) & 3u);
            m.w = expand2((bw1 >> 8) & 3u);
            ((uint4*)(buf + OFF_MASK))[tid] = m;
        }
        __syncthreads();

        const __half* jq = (const __half*)(buf + OFF_JQ);
        const __half* jt = (const __half*)(buf + OFF_JT);
        const uint4*  mk = (const uint4*)(buf + OFF_MASK);
        unsigned gtb = sbase + (t & 1) * BUF_SZ + OFF_GT;

#pragma unroll
        for (int ks = 0; ks < 8; ks++) {
            unsigned bf[8];
            ldsm_x4(bf,     gtb + lds_off0 + ks * 32);   // nt 0,1
            ldsm_x4(bf + 4, gtb + lds_off1 + ks * 32);   // nt 2,3

            int jo = hh * 128 + ks * 16 + tig * 2;
            unsigned qlo = *(const unsigned*)(jq + jo);
            unsigned qhi = *(const unsigned*)(jq + jo + 8);
            unsigned tlo = *(const unsigned*)(jt + jo);
            unsigned thi = *(const unsigned*)(jt + jo + 8);

            uint4 mm = mk[mtg * 256 + ks * 32 + gid * 4 + tig];

            unsigned a0 = wpair(P2[0], R2[0], qlo, tlo) & mm.x;
            unsigned a1 = wpair(P2[1], R2[1], qlo, tlo) & mm.y;
            unsigned a2 = wpair(P2[0], R2[0], qhi, thi) & mm.z;
            unsigned a3 = wpair(P2[1], R2[1], qhi, thi) & mm.w;

#pragma unroll
            for (int nt = 0; nt < 4; nt++)
                mma16816(c[nt], a0, a1, a2, a3, bf[nt * 2], bf[nt * 2 + 1]);
            mma16816(cz, a0, a1, a2, a3, ONES, ONES);
        }
    }

    // ---- epilogue ----
#pragma unroll
    for (int nt = 0; nt < 4; nt++) {
        int r0 = i0 + mtg * 16 + gid;
        int col = hh * 32 + nt * 8 + tig * 2;
        *(float2*)(&num_part[chunk][r0][col])     = make_float2(c[nt][0], c[nt][1]);
        *(float2*)(&num_part[chunk][r0 + 8][col]) = make_float2(c[nt][2], c[nt][3]);
    }
    if (tig == 0) {
        int r0 = i0 + mtg * 16 + gid;
        z_part[chunk][hh][r0]     = cz[0];
        z_part[chunk][hh][r0 + 8] = cz[2];
    }
}

// ---------------- kernel 3: combine + divide (float4) ----------------
__global__ __launch_bounds__(256) void finalize(float* __restrict__ out) {
    int idx = blockIdx.x * 256 + threadIdx.x;     // 262144 float4s
    int i = idx >> 6, c4 = idx & 63;
    int head = c4 >> 3;
    float4 n0 = *(const float4*)&num_part[0][i][c4 * 4];
    float4 n1 = *(const float4*)&num_part[1][i][c4 * 4];
    float zz = z_part[0][head][i] + z_part[1][head][i];
    float inv = 1.f / zz;
    float4 o;
    o.x = (n0.x + n1.x) * inv;
    o.y = (n0.y + n1.y) * inv;
    o.z = (n0.z + n1.z) * inv;
    o.w = (n0.w + n1.w) * inv;
    *(float4*)&out[(size_t)i * OUTF + c4 * 4] = o;
}

// ---------------- launcher ----------------
extern "C" void kernel_launch(void* const* d_in, const int* in_sizes, int n_in,
                              void* d_out, int out_size) {
    const float* h   = (const float*)d_in[0];
    const int*   adj = (const int*)d_in[1];
    const float* W   = (const float*)d_in[2];
    const float* a   = (const float*)d_in[3];
    float* out = (float*)d_out;

    cudaFuncSetAttribute(attn_agg, cudaFuncAttributeMaxDynamicSharedMemorySize, SMEM2_SZ);

    adj_to_bits<<<2048, 256>>>(adj);
    compute_wa<<<32, 256>>>(W, a);
    node_stats2<<<256, 256>>>(h);
    gemm_g<<<dim3(4, 32), 256>>>(h, W);
    attn_agg<<<dim3(NCHUNK, 64), 1024, SMEM2_SZ>>>();
    finalize<<<1024, 256>>>(out);
}

// round 11
// speedup vs baseline: 2.8052x; 1.1293x over previous
#include <cuda_runtime.h>
#include <cuda_fp16.h>

#define N_NODES 4096
#define HEADS   8
#define OUTF    256
#define NCHUNK  2
#define JT      128
#define ITILE   64
#define JCHUNK  (N_NODES / NCHUNK)
#define NTILES  (JCHUNK / JT)

// ---------------- device scratch ----------------
__device__ __align__(16) __half   g_h_t[OUTF * N_NODES];       // [h*32+f][n] fp16
__device__ __align__(16) float    Wa_g[256 * 16];              // [k][head + 8*dst]
__device__ __align__(16) __half2  PR_g[HEADS * N_NODES];       // (exp(s_src), exp(.2 s_src))
__device__ __align__(16) __half   qg[HEADS * N_NODES];         // exp(s_dst)
__device__ __align__(16) __half   tg[HEADS * N_NODES];         // exp(.2 s_dst)
__device__ __align__(16) unsigned adj_bits[N_NODES * (N_NODES / 32)];
__device__ __align__(16) float    num_part[NCHUNK][N_NODES][OUTF];
__device__ __align__(16) float    z_part[NCHUNK][HEADS][N_NODES];

// ---------------- kernel 0: adjacency -> bitmask ----------------
__global__ __launch_bounds__(256) void adj_to_bits(const int* __restrict__ adj) {
    int warp = threadIdx.x >> 5, lane = threadIdx.x & 31;
    int gw = blockIdx.x * 8 + warp;
    int i = gw >> 2, wbase = (gw & 3) * 32;
#pragma unroll 8
    for (int k = 0; k < 32; k++) {
        int v = adj[(size_t)i * N_NODES + (wbase + k) * 32 + lane];
        unsigned b = __ballot_sync(0xffffffffu, v != 0);
        if (lane == 0) adj_bits[i * 128 + wbase + k] = b;
    }
}

// ---------------- kernel A: Wa[k][c] = sum_f W[k, h*32+f] * a[dst*32+f] ----------------
__global__ __launch_bounds__(256) void compute_wa(const float* __restrict__ W,
                                                  const float* __restrict__ a) {
    int warp = threadIdx.x >> 5, lane = threadIdx.x & 31;
    int k = blockIdx.x * 8 + warp;
    float wrow[8];
#pragma unroll
    for (int hd = 0; hd < 8; hd++) wrow[hd] = W[(size_t)k * 256 + hd * 32 + lane];
    float asrc = a[lane], adst = a[32 + lane];
#pragma unroll
    for (int c = 0; c < 16; c++) {
        float v = wrow[c & 7] * ((c < 8) ? asrc : adst);
#pragma unroll
        for (int o = 16; o; o >>= 1) v += __shfl_xor_sync(0xffffffffu, v, o);
        if (lane == 0) Wa_g[k * 16 + c] = v;
    }
}

// ---------------- kernel B: node scores s = h @ Wa -> PR/q/t ----------------
__global__ __launch_bounds__(256) void node_stats2(const float* __restrict__ h) {
    __shared__ float sh_h[16][257];
    __shared__ float sh_wa[256][17];
    int tid = threadIdx.x;
    int n0 = blockIdx.x * 16;
#pragma unroll
    for (int q = 0; q < 16; q++) {
        int idx = q * 256 + tid;
        sh_h[idx >> 8][idx & 255] = h[(size_t)n0 * 256 + idx];
        sh_wa[idx >> 4][idx & 15] = Wa_g[idx];
    }
    __syncthreads();
    int nl = tid >> 4, c = tid & 15;
    float s = 0.f;
#pragma unroll 8
    for (int k = 0; k < 256; k++) s += sh_h[nl][k] * sh_wa[k][c];
    int n = n0 + nl;
    if (c < 8) {
        PR_g[c * N_NODES + n] = __floats2half2_rn(expf(s), expf(0.2f * s));
    } else {
        qg[(c - 8) * N_NODES + n] = __float2half(expf(s));
        tg[(c - 8) * N_NODES + n] = __float2half(expf(0.2f * s));
    }
}

// ---------------- kernel 1: g = h @ W via tf32 tensor cores -> fp16 g_h_t ----------------
__device__ __forceinline__ unsigned tf32r(float x) {
    unsigned y;
    asm("cvt.rna.tf32.f32 %0, %1;" : "=r"(y) : "f"(x));
    return y;
}

__device__ __forceinline__ void mma_tf32(float* c, unsigned a0, unsigned a1,
                                         unsigned a2, unsigned a3,
                                         unsigned b0, unsigned b1) {
    asm volatile(
        "mma.sync.aligned.m16n8k8.row.col.f32.tf32.tf32.f32 "
        "{%0,%1,%2,%3}, {%4,%5,%6,%7}, {%8,%9}, {%0,%1,%2,%3};"
        : "+f"(c[0]), "+f"(c[1]), "+f"(c[2]), "+f"(c[3])
        : "r"(a0), "r"(a1), "r"(a2), "r"(a3), "r"(b0), "r"(b1));
}

// dynamic smem: sh_w [256][36] u32 (36864 B) | sh_h [2][128][36] u32 (36864 B)
#define GEMM_SMEM (36864 + 36864)

__global__ __launch_bounds__(256, 1) void gemm_g_tc(const float* __restrict__ h,
                                                    const float* __restrict__ W) {
    extern __shared__ unsigned smg[];
    unsigned* sh_w = smg;                    // [k(256)][36], n-slice of W (tf32 bits)
    unsigned* sh_h = smg + 256 * 36;         // [2][m(128)][36] (tf32 bits)
    __half* tT = (__half*)smg;               // epilogue alias: [32][136] halves (272B rows)

    int tid = threadIdx.x;
    int warp = tid >> 5, lane = tid & 31;
    int gid = lane >> 2, tig = lane & 3;
    int wm = warp >> 1, wn = warp & 1;       // warp tile: m 32, n 16
    int n0 = blockIdx.x * 32, m0 = blockIdx.y * 128;

    // stage W[:, n0:n0+32] -> tf32
#pragma unroll
    for (int i = 0; i < 8; i++) {
        int idx = i * 256 + tid;             // 2048 float4s
        int k = idx >> 3, seg = idx & 7;
        float4 v = *(const float4*)&W[(size_t)k * 256 + n0 + seg * 4];
        uint4 u = make_uint4(tf32r(v.x), tf32r(v.y), tf32r(v.z), tf32r(v.w));
        *(uint4*)&sh_w[k * 36 + seg * 4] = u;
    }

    float4 hreg[4];
    auto ldh = [&](int kc) {
#pragma unroll
        for (int i = 0; i < 4; i++) {
            int idx = i * 256 + tid;
            int m = idx >> 3, seg = idx & 7;
            hreg[i] = *(const float4*)&h[(size_t)(m0 + m) * 256 + kc * 32 + seg * 4];
        }
    };
    auto sth = [&](int b) {
        unsigned* dst = sh_h + b * 128 * 36;
#pragma unroll
        for (int i = 0; i < 4; i++) {
            int idx = i * 256 + tid;
            int m = idx >> 3, seg = idx & 7;
            float4 v = hreg[i];
            uint4 u = make_uint4(tf32r(v.x), tf32r(v.y), tf32r(v.z), tf32r(v.w));
            *(uint4*)&dst[m * 36 + seg * 4] = u;
        }
    };

    float c[2][2][4] = {};

    ldh(0);
    for (int kc = 0; kc < 8; kc++) {
        sth(kc & 1);
        __syncthreads();
        if (kc < 7) ldh(kc + 1);

        const unsigned* A = sh_h + (kc & 1) * 128 * 36;
#pragma unroll
        for (int ks = 0; ks < 4; ks++) {
            unsigned b0[2], b1[2];
#pragma unroll
            for (int nt = 0; nt < 2; nt++) {
                int nn = wn * 16 + nt * 8 + gid;
                int kb = kc * 32 + ks * 8 + tig;          // B advances with k-chunk
                b0[nt] = sh_w[kb * 36 + nn];
                b1[nt] = sh_w[(kb + 4) * 36 + nn];
            }
#pragma unroll
            for (int mt = 0; mt < 2; mt++) {
                int r0 = (wm * 32 + mt * 16 + gid) * 36 + ks * 8 + tig;
                unsigned a0 = A[r0];
                unsigned a1 = A[r0 + 8 * 36];
                unsigned a2 = A[r0 + 4];
                unsigned a3 = A[r0 + 8 * 36 + 4];
#pragma unroll
                for (int nt = 0; nt < 2; nt++)
                    mma_tf32(c[mt][nt], a0, a1, a2, a3, b0[nt], b1[nt]);
            }
        }
        __syncthreads();
    }

    // epilogue: fragments -> tT[n][m] halves -> coalesced global (transposed)
#pragma unroll
    for (int mt = 0; mt < 2; mt++)
#pragma unroll
        for (int nt = 0; nt < 2; nt++) {
            int nn = wn * 16 + nt * 8 + tig * 2;
            int mm = wm * 32 + mt * 16 + gid;
            tT[nn * 136 + mm]           = __float2half(c[mt][nt][0]);
            tT[(nn + 1) * 136 + mm]     = __float2half(c[mt][nt][1]);
            tT[nn * 136 + mm + 8]       = __float2half(c[mt][nt][2]);
            tT[(nn + 1) * 136 + mm + 8] = __float2half(c[mt][nt][3]);
        }
    __syncthreads();
#pragma unroll
    for (int i = 0; i < 2; i++) {
        int idx = i * 256 + tid;             // 512 int4s = 32 n x 16 segs
        int nn = idx >> 4, seg = idx & 15;
        *(int4*)&g_h_t[(size_t)(n0 + nn) * N_NODES + m0 + seg * 8] =
            *(int4*)&tT[nn * 136 + seg * 8];
    }
}

// ---------------- kernel 2 helpers ----------------
__device__ __forceinline__ void mma16816(float* c, unsigned a0, unsigned a1,
                                         unsigned a2, unsigned a3,
                                         unsigned b0, unsigned b1) {
    asm volatile(
        "mma.sync.aligned.m16n8k16.row.col.f32.f16.f16.f32 "
        "{%0,%1,%2,%3}, {%4,%5,%6,%7}, {%8,%9}, {%0,%1,%2,%3};"
        : "+f"(c[0]), "+f"(c[1]), "+f"(c[2]), "+f"(c[3])
        : "r"(a0), "r"(a1), "r"(a2), "r"(a3), "r"(b0), "r"(b1));
}

__device__ __forceinline__ void ldsm_x4(unsigned* r, unsigned addr) {
    asm volatile(
        "ldmatrix.sync.aligned.m8n8.x4.shared.b16 {%0,%1,%2,%3}, [%4];"
        : "=r"(r[0]), "=r"(r[1]), "=r"(r[2]), "=r"(r[3]) : "r"(addr));
}

__device__ __forceinline__ unsigned expand2(unsigned b) {
    return (b & 1u) * 0xFFFFu + (b & 2u) * 0x7FFF8000u;
}

__device__ __forceinline__ unsigned wpair(__half2 P2, __half2 R2,
                                          unsigned q2, unsigned t2) {
    __half2 qq = *(__half2*)&q2, tt = *(__half2*)&t2;
    __half2 u = __hmax2(__hmul2(P2, qq), __hmul2(R2, tt));
    return *(unsigned*)&u;
}

__device__ __forceinline__ void cp_async4(unsigned dst, const void* src) {
    asm volatile("cp.async.ca.shared.global [%0], [%1], 4;" :: "r"(dst), "l"(src));
}
__device__ __forceinline__ void cp_async8(unsigned dst, const void* src) {
    asm volatile("cp.async.ca.shared.global [%0], [%1], 8;" :: "r"(dst), "l"(src));
}
__device__ __forceinline__ void cp_commit() {
    asm volatile("cp.async.commit_group;" ::: "memory");
}
__device__ __forceinline__ void cp_wait0() {
    asm volatile("cp.async.wait_group 0;" ::: "memory");
}

// buffer: gTs 69632 | jq 2048 | jt 2048 | adjb 1024 | masks 16384 = 91136 ; x2
#define OFF_GT     0
#define OFF_JQ     69632
#define OFF_JT     71680
#define OFF_ADJB   73728
#define OFF_MASK   74752
#define BUF_SZ     91136
#define SMEM2_SZ   (2 * BUF_SZ)

extern __shared__ char smem2[];

__global__ __launch_bounds__(1024, 1) void attn_agg() {
    int tid  = threadIdx.x;
    int warp = tid >> 5, lane = tid & 31;
    int gid  = lane >> 2, tig = lane & 3;
    int hh   = warp & 7;
    int mtg  = warp >> 3;          // 0..3, one m16 tile per warp
    int i0   = blockIdx.y * ITILE;
    int chunk = blockIdx.x;
    int jstart = chunk * JCHUNK;

    unsigned sbase = (unsigned)__cvta_generic_to_shared(smem2);

    auto stage = [&](int t) {
        int j0 = jstart + t * JT;
        unsigned b = sbase + (t & 1) * BUF_SZ;
#pragma unroll
        for (int q = 0; q < 8; q++) {             // gTs: 8192 x 8B
            int idx = q * 1024 + tid;
            int hf = idx >> 5, j4 = idx & 31;
            cp_async8(b + OFF_GT + (hf * 136 + j4 * 4) * 2,
                      &g_h_t[(size_t)hf * N_NODES + j0 + j4 * 4]);
        }
        if (tid < 512) {                          // jq, jt: 512 x 4B each
            int h2 = tid >> 6, o = tid & 63;
            cp_async4(b + OFF_JQ + tid * 4, &qg[h2 * N_NODES + j0 + o * 2]);
            cp_async4(b + OFF_JT + tid * 4, &tg[h2 * N_NODES + j0 + o * 2]);
        }
        if (tid < 256) {                          // adjb raw: 64 rows x 4 words
            int r = tid >> 2, cw = tid & 3;
            cp_async4(b + OFF_ADJB + tid * 4,
                      &adj_bits[(i0 + r) * 128 + (j0 >> 5) + cw]);
        }
        cp_commit();
    };

    // per-row broadcast params (2 rows per warp: gid, gid+8 within m16 tile)
    __half2 P2[2], R2[2];
#pragma unroll
    for (int rh = 0; rh < 2; rh++) {
        int r = i0 + mtg * 16 + rh * 8 + gid;
        __half2 pr = PR_g[hh * N_NODES + r];
        P2[rh] = __half2half2(__low2half(pr));
        R2[rh] = __half2half2(__high2half(pr));
    }

    // ldmatrix per-lane base byte-offsets within gTs
    int ntl = lane >> 4, hb = (lane >> 3) & 1, rowl = lane & 7;
    unsigned lds_off0 = ((hh * 32 + ntl * 8 + rowl) * 136 + hb * 8) * 2;
    unsigned lds_off1 = lds_off0 + 16 * 136 * 2;

    float c[4][4] = {};
    float cz[4] = {};
    const unsigned ONES = 0x3C003C00u;

    // mask-expansion indices for this thread (1024 groups, one each)
    int emtg = tid >> 8, eks = (tid >> 5) & 7, egid = (tid >> 2) & 7, etig = tid & 3;
    int ewc = eks >> 1, esh = (eks & 1) * 16 + etig * 2;

    stage(0);

    for (int t = 0; t < NTILES; t++) {
        cp_wait0();
        __syncthreads();
        if (t + 1 < NTILES) stage(t + 1);

        char* buf = smem2 + (t & 1) * BUF_SZ;
        {   // expand adjacency bits -> per-fragment AND masks (once per tile)
            const unsigned* adjb = (const unsigned*)(buf + OFF_ADJB);
            unsigned bw0 = adjb[(emtg * 16 + egid) * 4 + ewc] >> esh;
            unsigned bw1 = adjb[(emtg * 16 + egid + 8) * 4 + ewc] >> esh;
            uint4 m;
            m.x = expand2(bw0 & 3u);
            m.y = expand2(bw1 & 3u);
            m.z = expand2((bw0 >> 8) & 3u);
            m.w = expand2((bw1 >> 8) & 3u);
            ((uint4*)(buf + OFF_MASK))[tid] = m;
        }
        __syncthreads();

        const __half* jq = (const __half*)(buf + OFF_JQ);
        const __half* jt = (const __half*)(buf + OFF_JT);
        const uint4*  mk = (const uint4*)(buf + OFF_MASK);
        unsigned gtb = sbase + (t & 1) * BUF_SZ + OFF_GT;

#pragma unroll
        for (int ks = 0; ks < 8; ks++) {
            unsigned bf[8];
            ldsm_x4(bf,     gtb + lds_off0 + ks * 32);   // nt 0,1
            ldsm_x4(bf + 4, gtb + lds_off1 + ks * 32);   // nt 2,3

            int jo = hh * 128 + ks * 16 + tig * 2;
            unsigned qlo = *(const unsigned*)(jq + jo);
            unsigned qhi = *(const unsigned*)(jq + jo + 8);
            unsigned tlo = *(const unsigned*)(jt + jo);
            unsigned thi = *(const unsigned*)(jt + jo + 8);

            uint4 mm = mk[mtg * 256 + ks * 32 + gid * 4 + tig];

            unsigned a0 = wpair(P2[0], R2[0], qlo, tlo) & mm.x;
            unsigned a1 = wpair(P2[1], R2[1], qlo, tlo) & mm.y;
            unsigned a2 = wpair(P2[0], R2[0], qhi, thi) & mm.z;
            unsigned a3 = wpair(P2[1], R2[1], qhi, thi) & mm.w;

#pragma unroll
            for (int nt = 0; nt < 4; nt++)
                mma16816(c[nt], a0, a1, a2, a3, bf[nt * 2], bf[nt * 2 + 1]);
            mma16816(cz, a0, a1, a2, a3, ONES, ONES);
        }
    }

    // ---- epilogue ----
#pragma unroll
    for (int nt = 0; nt < 4; nt++) {
        int r0 = i0 + mtg * 16 + gid;
        int col = hh * 32 + nt * 8 + tig * 2;
        *(float2*)(&num_part[chunk][r0][col])     = make_float2(c[nt][0], c[nt][1]);
        *(float2*)(&num_part[chunk][r0 + 8][col]) = make_float2(c[nt][2], c[nt][3]);
    }
    if (tig == 0) {
        int r0 = i0 + mtg * 16 + gid;
        z_part[chunk][hh][r0]     = cz[0];
        z_part[chunk][hh][r0 + 8] = cz[2];
    }
}

// ---------------- kernel 3: combine + divide (float4) ----------------
__global__ __launch_bounds__(256) void finalize(float* __restrict__ out) {
    int idx = blockIdx.x * 256 + threadIdx.x;     // 262144 float4s
    int i = idx >> 6, c4 = idx & 63;
    int head = c4 >> 3;
    float4 n0 = *(const float4*)&num_part[0][i][c4 * 4];
    float4 n1 = *(const float4*)&num_part[1][i][c4 * 4];
    float zz = z_part[0][head][i] + z_part[1][head][i];
    float inv = 1.f / zz;
    float4 o;
    o.x = (n0.x + n1.x) * inv;
    o.y = (n0.y + n1.y) * inv;
    o.z = (n0.z + n1.z) * inv;
    o.w = (n0.w + n1.w) * inv;
    *(float4*)&out[(size_t)i * OUTF + c4 * 4] = o;
}

// ---------------- launcher ----------------
extern "C" void kernel_launch(void* const* d_in, const int* in_sizes, int n_in,
                              void* d_out, int out_size) {
    const float* h   = (const float*)d_in[0];
    const int*   adj = (const int*)d_in[1];
    const float* W   = (const float*)d_in[2];
    const float* a   = (const float*)d_in[3];
    float* out = (float*)d_out;

    cudaFuncSetAttribute(attn_agg, cudaFuncAttributeMaxDynamicSharedMemorySize, SMEM2_SZ);
    cudaFuncSetAttribute(gemm_g_tc, cudaFuncAttributeMaxDynamicSharedMemorySize, GEMM_SMEM);

    adj_to_bits<<<2048, 256>>>(adj);
    compute_wa<<<32, 256>>>(W, a);
    node_stats2<<<256, 256>>>(h);
    gemm_g_tc<<<dim3(8, 32), 256, GEMM_SMEM>>>(h, W);
    attn_agg<<<dim3(NCHUNK, 64), 1024, SMEM2_SZ>>>();
    finalize<<<1024, 256>>>(out);
}

// round 12
// speedup vs baseline: 2.8662x; 1.0217x over previous
#include <cuda_runtime.h>
#include <cuda_fp16.h>

#define N_NODES 4096
#define HEADS   8
#define OUTF    256
#define NCHUNK  2
#define JT      128
#define ITILE   64
#define JCHUNK  (N_NODES / NCHUNK)
#define NTILES  (JCHUNK / JT)

// ---------------- device scratch ----------------
__device__ __align__(16) __half   g_h_t[OUTF * N_NODES];       // [h*32+f][n] fp16
__device__ __align__(16) float    Wa_g[256 * 16];
__device__ __align__(16) __half2  PR_g[HEADS * N_NODES];
__device__ __align__(16) __half   qg[HEADS * N_NODES];
__device__ __align__(16) __half   tg[HEADS * N_NODES];
__device__ __align__(16) unsigned adj_bits[N_NODES * (N_NODES / 32)];
__device__ __align__(16) float    num_part[NCHUNK][N_NODES][OUTF];
__device__ __align__(16) float    z_part[NCHUNK][HEADS][N_NODES];

// ---------------- kernel 0: adjacency -> bitmask ----------------
__global__ __launch_bounds__(256) void adj_to_bits(const int* __restrict__ adj) {
    int warp = threadIdx.x >> 5, lane = threadIdx.x & 31;
    int gw = blockIdx.x * 8 + warp;
    int i = gw >> 2, wbase = (gw & 3) * 32;
#pragma unroll 8
    for (int k = 0; k < 32; k++) {
        int v = adj[(size_t)i * N_NODES + (wbase + k) * 32 + lane];
        unsigned b = __ballot_sync(0xffffffffu, v != 0);
        if (lane == 0) adj_bits[i * 128 + wbase + k] = b;
    }
}

// ---------------- kernel A: Wa ----------------
__global__ __launch_bounds__(256) void compute_wa(const float* __restrict__ W,
                                                  const float* __restrict__ a) {
    int warp = threadIdx.x >> 5, lane = threadIdx.x & 31;
    int k = blockIdx.x * 8 + warp;
    float wrow[8];
#pragma unroll
    for (int hd = 0; hd < 8; hd++) wrow[hd] = W[(size_t)k * 256 + hd * 32 + lane];
    float asrc = a[lane], adst = a[32 + lane];
#pragma unroll
    for (int c = 0; c < 16; c++) {
        float v = wrow[c & 7] * ((c < 8) ? asrc : adst);
#pragma unroll
        for (int o = 16; o; o >>= 1) v += __shfl_xor_sync(0xffffffffu, v, o);
        if (lane == 0) Wa_g[k * 16 + c] = v;
    }
}

// ---------------- kernel B: node scores ----------------
__global__ __launch_bounds__(256) void node_stats2(const float* __restrict__ h) {
    __shared__ float sh_h[16][257];
    __shared__ float sh_wa[256][17];
    int tid = threadIdx.x;
    int n0 = blockIdx.x * 16;
#pragma unroll
    for (int q = 0; q < 16; q++) {
        int idx = q * 256 + tid;
        sh_h[idx >> 8][idx & 255] = h[(size_t)n0 * 256 + idx];
        sh_wa[idx >> 4][idx & 15] = Wa_g[idx];
    }
    __syncthreads();
    int nl = tid >> 4, c = tid & 15;
    float s = 0.f;
#pragma unroll 8
    for (int k = 0; k < 256; k++) s += sh_h[nl][k] * sh_wa[k][c];
    int n = n0 + nl;
    if (c < 8) {
        PR_g[c * N_NODES + n] = __floats2half2_rn(expf(s), expf(0.2f * s));
    } else {
        qg[(c - 8) * N_NODES + n] = __float2half(expf(s));
        tg[(c - 8) * N_NODES + n] = __float2half(expf(0.2f * s));
    }
}

// ---------------- kernel 1: g = h @ W via tf32 (128m x 64n, single wave) ----------------
__device__ __forceinline__ unsigned tf32r(float x) {
    unsigned y;
    asm("cvt.rna.tf32.f32 %0, %1;" : "=r"(y) : "f"(x));
    return y;
}

__device__ __forceinline__ void mma_tf32(float* c, unsigned a0, unsigned a1,
                                         unsigned a2, unsigned a3,
                                         unsigned b0, unsigned b1) {
    asm volatile(
        "mma.sync.aligned.m16n8k8.row.col.f32.tf32.tf32.f32 "
        "{%0,%1,%2,%3}, {%4,%5,%6,%7}, {%8,%9}, {%0,%1,%2,%3};"
        : "+f"(c[0]), "+f"(c[1]), "+f"(c[2]), "+f"(c[3])
        : "r"(a0), "r"(a1), "r"(a2), "r"(a3), "r"(b0), "r"(b1));
}

// sh_w [256][68] u32 (69632 B) | sh_h [2][128][36] u32 (36864 B)
#define GEMM_SMEM (69632 + 36864)

__global__ __launch_bounds__(256, 1) void gemm_g_tc(const float* __restrict__ h,
                                                    const float* __restrict__ W) {
    extern __shared__ unsigned smg[];
    unsigned* sh_w = smg;                    // [k(256)][68]
    unsigned* sh_h = smg + 256 * 68;         // [2][m(128)][36]
    __half* tT = (__half*)smg;               // epilogue alias: [64][136] halves

    int tid = threadIdx.x;
    int warp = tid >> 5, lane = tid & 31;
    int gid = lane >> 2, tig = lane & 3;
    int wm = warp >> 1, wn = warp & 1;       // warp tile: m 32, n 32
    int n0 = blockIdx.x * 64, m0 = blockIdx.y * 128;

    // stage W[:, n0:n0+64] -> tf32 : 4096 float4
#pragma unroll
    for (int i = 0; i < 16; i++) {
        int idx = i * 256 + tid;
        int k = idx >> 4, seg = idx & 15;
        float4 v = *(const float4*)&W[(size_t)k * 256 + n0 + seg * 4];
        uint4 u = make_uint4(tf32r(v.x), tf32r(v.y), tf32r(v.z), tf32r(v.w));
        *(uint4*)&sh_w[k * 68 + seg * 4] = u;
    }

    float4 hreg[4];
    auto ldh = [&](int kc) {
#pragma unroll
        for (int i = 0; i < 4; i++) {
            int idx = i * 256 + tid;
            int m = idx >> 3, seg = idx & 7;
            hreg[i] = *(const float4*)&h[(size_t)(m0 + m) * 256 + kc * 32 + seg * 4];
        }
    };
    auto sth = [&](int b) {
        unsigned* dst = sh_h + b * 128 * 36;
#pragma unroll
        for (int i = 0; i < 4; i++) {
            int idx = i * 256 + tid;
            int m = idx >> 3, seg = idx & 7;
            float4 v = hreg[i];
            uint4 u = make_uint4(tf32r(v.x), tf32r(v.y), tf32r(v.z), tf32r(v.w));
            *(uint4*)&dst[m * 36 + seg * 4] = u;
        }
    };

    float c[2][4][4] = {};

    ldh(0);
    for (int kc = 0; kc < 8; kc++) {
        sth(kc & 1);
        __syncthreads();
        if (kc < 7) ldh(kc + 1);

        const unsigned* A = sh_h + (kc & 1) * 128 * 36;
#pragma unroll
        for (int ks = 0; ks < 4; ks++) {
            unsigned b0[4], b1[4];
            int kb = kc * 32 + ks * 8 + tig;
#pragma unroll
            for (int nt = 0; nt < 4; nt++) {
                int nn = wn * 32 + nt * 8 + gid;
                b0[nt] = sh_w[kb * 68 + nn];
                b1[nt] = sh_w[(kb + 4) * 68 + nn];
            }
#pragma unroll
            for (int mt = 0; mt < 2; mt++) {
                int r0 = (wm * 32 + mt * 16 + gid) * 36 + ks * 8 + tig;
                unsigned a0 = A[r0];
                unsigned a1 = A[r0 + 8 * 36];
                unsigned a2 = A[r0 + 4];
                unsigned a3 = A[r0 + 8 * 36 + 4];
#pragma unroll
                for (int nt = 0; nt < 4; nt++)
                    mma_tf32(c[mt][nt], a0, a1, a2, a3, b0[nt], b1[nt]);
            }
        }
        __syncthreads();
    }

    // epilogue: transpose via smem, coalesced stores
#pragma unroll
    for (int mt = 0; mt < 2; mt++)
#pragma unroll
        for (int nt = 0; nt < 4; nt++) {
            int nn = wn * 32 + nt * 8 + tig * 2;
            int mm = wm * 32 + mt * 16 + gid;
            tT[nn * 136 + mm]           = __float2half(c[mt][nt][0]);
            tT[(nn + 1) * 136 + mm]     = __float2half(c[mt][nt][1]);
            tT[nn * 136 + mm + 8]       = __float2half(c[mt][nt][2]);
            tT[(nn + 1) * 136 + mm + 8] = __float2half(c[mt][nt][3]);
        }
    __syncthreads();
#pragma unroll
    for (int i = 0; i < 4; i++) {
        int idx = i * 256 + tid;             // 1024 int4s = 64 n x 16 segs
        int nn = idx >> 4, seg = idx & 15;
        *(int4*)&g_h_t[(size_t)(n0 + nn) * N_NODES + m0 + seg * 8] =
            *(int4*)&tT[nn * 136 + seg * 8];
    }
}

// ---------------- kernel 2 helpers ----------------
__device__ __forceinline__ void mma16816(float* c, unsigned a0, unsigned a1,
                                         unsigned a2, unsigned a3,
                                         unsigned b0, unsigned b1) {
    asm volatile(
        "mma.sync.aligned.m16n8k16.row.col.f32.f16.f16.f32 "
        "{%0,%1,%2,%3}, {%4,%5,%6,%7}, {%8,%9}, {%0,%1,%2,%3};"
        : "+f"(c[0]), "+f"(c[1]), "+f"(c[2]), "+f"(c[3])
        : "r"(a0), "r"(a1), "r"(a2), "r"(a3), "r"(b0), "r"(b1));
}

__device__ __forceinline__ void ldsm_x4(unsigned* r, unsigned addr) {
    asm volatile(
        "ldmatrix.sync.aligned.m8n8.x4.shared.b16 {%0,%1,%2,%3}, [%4];"
        : "=r"(r[0]), "=r"(r[1]), "=r"(r[2]), "=r"(r[3]) : "r"(addr));
}

__device__ __forceinline__ unsigned expand2(unsigned b) {
    return (b & 1u) * 0xFFFFu + (b & 2u) * 0x7FFF8000u;
}

__device__ __forceinline__ unsigned wpair(__half2 P2, __half2 R2,
                                          unsigned q2, unsigned t2) {
    __half2 qq = *(__half2*)&q2, tt = *(__half2*)&t2;
    __half2 u = __hmax2(__hmul2(P2, qq), __hmul2(R2, tt));
    return *(unsigned*)&u;
}

__device__ __forceinline__ void cp_async4(unsigned dst, const void* src) {
    asm volatile("cp.async.ca.shared.global [%0], [%1], 4;" :: "r"(dst), "l"(src));
}
__device__ __forceinline__ void cp_async8(unsigned dst, const void* src) {
    asm volatile("cp.async.ca.shared.global [%0], [%1], 8;" :: "r"(dst), "l"(src));
}
__device__ __forceinline__ void cp_commit() {
    asm volatile("cp.async.commit_group;" ::: "memory");
}
__device__ __forceinline__ void cp_wait0() {
    asm volatile("cp.async.wait_group 0;" ::: "memory");
}

// buffer (4 heads): gTs 34816 | jq 1024 | jt 1024 | adjb 1024 | masks 16384 = 54272 ; x2
#define OFF_GT     0
#define OFF_JQ     34816
#define OFF_JT     35840
#define OFF_ADJB   36864
#define OFF_MASK   37888
#define BUF_SZ     54272
#define SMEM2_SZ   (2 * BUF_SZ)

extern __shared__ char smem2[];

// grid (4, 64): bx&1 = head-group, bx>>1 = chunk. 512 threads, 2 CTAs/SM.
__global__ __launch_bounds__(512, 2) void attn_agg() {
    int tid  = threadIdx.x;
    int warp = tid >> 5, lane = tid & 31;
    int gid  = lane >> 2, tig = lane & 3;
    int lh   = warp & 3;           // local head (0..3)
    int mtg  = warp >> 2;          // m16 tile (0..3)
    int hg   = blockIdx.x & 1;     // head group
    int chunk = blockIdx.x >> 1;
    int ghead = hg * 4 + lh;
    int i0   = blockIdx.y * ITILE;
    int jstart = chunk * JCHUNK;

    unsigned sbase = (unsigned)__cvta_generic_to_shared(smem2);

    auto stage = [&](int t) {
        int j0 = jstart + t * JT;
        unsigned b = sbase + (t & 1) * BUF_SZ;
#pragma unroll
        for (int q = 0; q < 8; q++) {             // gTs: 4096 x 8B (4 heads x 32 f)
            int idx = q * 512 + tid;
            int hf = idx >> 5, j4 = idx & 31;
            cp_async8(b + OFF_GT + (hf * 136 + j4 * 4) * 2,
                      &g_h_t[(size_t)(hg * 128 + hf) * N_NODES + j0 + j4 * 4]);
        }
        if (tid < 256) {                          // jq, jt: 256 x 4B each
            int h2 = tid >> 6, o = tid & 63;
            cp_async4(b + OFF_JQ + tid * 4, &qg[(hg * 4 + h2) * N_NODES + j0 + o * 2]);
            cp_async4(b + OFF_JT + tid * 4, &tg[(hg * 4 + h2) * N_NODES + j0 + o * 2]);
        }
        if (tid < 256) {                          // adjb raw: 64 rows x 4 words
            int r = tid >> 2, cw = tid & 3;
            cp_async4(b + OFF_ADJB + tid * 4,
                      &adj_bits[(i0 + r) * 128 + (j0 >> 5) + cw]);
        }
        cp_commit();
    };

    // per-row broadcast params
    __half2 P2[2], R2[2];
#pragma unroll
    for (int rh = 0; rh < 2; rh++) {
        int r = i0 + mtg * 16 + rh * 8 + gid;
        __half2 pr = PR_g[ghead * N_NODES + r];
        P2[rh] = __half2half2(__low2half(pr));
        R2[rh] = __half2half2(__high2half(pr));
    }

    // ldmatrix per-lane base offsets (local head rows)
    int ntl = lane >> 4, hb = (lane >> 3) & 1, rowl = lane & 7;
    unsigned lds_off0 = ((lh * 32 + ntl * 8 + rowl) * 136 + hb * 8) * 2;
    unsigned lds_off1 = lds_off0 + 16 * 136 * 2;

    float c[4][4] = {};
    float cz[4] = {};
    const unsigned ONES = 0x3C003C00u;

    stage(0);

    for (int t = 0; t < NTILES; t++) {
        cp_wait0();
        __syncthreads();
        if (t + 1 < NTILES) stage(t + 1);

        char* buf = smem2 + (t & 1) * BUF_SZ;
        {   // expand adjacency bits -> per-fragment AND masks (2 slots/thread)
            const unsigned* adjb = (const unsigned*)(buf + OFF_ADJB);
#pragma unroll
            for (int q = 0; q < 2; q++) {
                int slot = q * 512 + tid;
                int emtg = slot >> 8, eks = (slot >> 5) & 7;
                int egid = (slot >> 2) & 7, etig = slot & 3;
                int ewc = eks >> 1, esh = (eks & 1) * 16 + etig * 2;
                unsigned bw0 = adjb[(emtg * 16 + egid) * 4 + ewc] >> esh;
                unsigned bw1 = adjb[(emtg * 16 + egid + 8) * 4 + ewc] >> esh;
                uint4 m;
                m.x = expand2(bw0 & 3u);
                m.y = expand2(bw1 & 3u);
                m.z = expand2((bw0 >> 8) & 3u);
                m.w = expand2((bw1 >> 8) & 3u);
                ((uint4*)(buf + OFF_MASK))[slot] = m;
            }
        }
        __syncthreads();

        const __half* jq = (const __half*)(buf + OFF_JQ);
        const __half* jt = (const __half*)(buf + OFF_JT);
        const uint4*  mk = (const uint4*)(buf + OFF_MASK);
        unsigned gtb = sbase + (t & 1) * BUF_SZ + OFF_GT;

#pragma unroll
        for (int ks = 0; ks < 8; ks++) {
            unsigned bf[8];
            ldsm_x4(bf,     gtb + lds_off0 + ks * 32);   // nt 0,1
            ldsm_x4(bf + 4, gtb + lds_off1 + ks * 32);   // nt 2,3

            int jo = lh * 128 + ks * 16 + tig * 2;
            unsigned qlo = *(const unsigned*)(jq + jo);
            unsigned qhi = *(const unsigned*)(jq + jo + 8);
            unsigned tlo = *(const unsigned*)(jt + jo);
            unsigned thi = *(const unsigned*)(jt + jo + 8);

            uint4 mm = mk[mtg * 256 + ks * 32 + gid * 4 + tig];

            unsigned a0 = wpair(P2[0], R2[0], qlo, tlo) & mm.x;
            unsigned a1 = wpair(P2[1], R2[1], qlo, tlo) & mm.y;
            unsigned a2 = wpair(P2[0], R2[0], qhi, thi) & mm.z;
            unsigned a3 = wpair(P2[1], R2[1], qhi, thi) & mm.w;

#pragma unroll
            for (int nt = 0; nt < 4; nt++)
                mma16816(c[nt], a0, a1, a2, a3, bf[nt * 2], bf[nt * 2 + 1]);
            mma16816(cz, a0, a1, a2, a3, ONES, ONES);
        }
    }

    // ---- epilogue ----
#pragma unroll
    for (int nt = 0; nt < 4; nt++) {
        int r0 = i0 + mtg * 16 + gid;
        int col = ghead * 32 + nt * 8 + tig * 2;
        *(float2*)(&num_part[chunk][r0][col])     = make_float2(c[nt][0], c[nt][1]);
        *(float2*)(&num_part[chunk][r0 + 8][col]) = make_float2(c[nt][2], c[nt][3]);
    }
    if (tig == 0) {
        int r0 = i0 + mtg * 16 + gid;
        z_part[chunk][ghead][r0]     = cz[0];
        z_part[chunk][ghead][r0 + 8] = cz[2];
    }
}

// ---------------- kernel 3: combine + divide (float4) ----------------
__global__ __launch_bounds__(256) void finalize(float* __restrict__ out) {
    int idx = blockIdx.x * 256 + threadIdx.x;
    int i = idx >> 6, c4 = idx & 63;
    int head = c4 >> 3;
    float4 n0 = *(const float4*)&num_part[0][i][c4 * 4];
    float4 n1 = *(const float4*)&num_part[1][i][c4 * 4];
    float zz = z_part[0][head][i] + z_part[1][head][i];
    float inv = 1.f / zz;
    float4 o;
    o.x = (n0.x + n1.x) * inv;
    o.y = (n0.y + n1.y) * inv;
    o.z = (n0.z + n1.z) * inv;
    o.w = (n0.w + n1.w) * inv;
    *(float4*)&out[(size_t)i * OUTF + c4 * 4] = o;
}

// ---------------- launcher ----------------
extern "C" void kernel_launch(void* const* d_in, const int* in_sizes, int n_in,
                              void* d_out, int out_size) {
    const float* h   = (const float*)d_in[0];
    const int*   adj = (const int*)d_in[1];
    const float* W   = (const float*)d_in[2];
    const float* a   = (const float*)d_in[3];
    float* out = (float*)d_out;

    cudaFuncSetAttribute(attn_agg, cudaFuncAttributeMaxDynamicSharedMemorySize, SMEM2_SZ);
    cudaFuncSetAttribute(gemm_g_tc, cudaFuncAttributeMaxDynamicSharedMemorySize, GEMM_SMEM);

    adj_to_bits<<<2048, 256>>>(adj);
    compute_wa<<<32, 256>>>(W, a);
    node_stats2<<<256, 256>>>(h);
    gemm_g_tc<<<dim3(4, 32), 256, GEMM_SMEM>>>(h, W);
    attn_agg<<<dim3(4, 64), 512, SMEM2_SZ>>>();
    finalize<<<1024, 256>>>(out);
}